// round 14
// baseline (speedup 1.0000x reference)
#include <cuda_runtime.h>
#include <cstdint>
#include <cmath>

// ---------------- problem constants ----------------
#define N_NODES   20000
#define N_EDGES   320000
#define N_GRAPHS  200
#define MAXN      100
#define NPAIR     4950          // 100*99/2
#define IN_DIM    128
#define H_DIM     256
#define L_DIM     64

// ---------------- scratch (device globals; no allocation allowed) ----------
__device__ __align__(128) int   g_hist[N_NODES];            // in-degree
__device__ __align__(128) int   g_off [N_NODES];            // CSR exclusive offsets
__device__ __align__(128) int   g_cur [N_NODES];            // fill cursors
__device__ __align__(128) int   g_csr [N_EDGES];            // src ids grouped by dst
__device__ __align__(128) float g_dinv[N_NODES];            // rsqrt(deg+1)
__device__ __align__(128) float g_u   [N_NODES * H_DIM];    // (A@W)*dinv[row]
__device__ __align__(128) float g_h   [N_NODES * H_DIM];    // conv1 output
__device__ __align__(128) float g_sums[N_GRAPHS * H_DIM];
__device__ __align__(128) float g_cnt [N_GRAPHS];
__device__ __align__(128) float g_hg  [N_GRAPHS * H_DIM];
__device__ __align__(128) float g_z   [N_GRAPHS * L_DIM];
__device__ __align__(128) float g_d1  [N_GRAPHS * H_DIM];
__device__ __align__(128) float g_d2  [N_GRAPHS * H_DIM];
__device__ __align__(128) int   g_pi  [NPAIR];
__device__ __align__(128) int   g_pj  [NPAIR];

// ---------------- zero scratch ----------------
__global__ void zero_kernel() {
    int i = blockIdx.x * blockDim.x + threadIdx.x;
    if (i < N_NODES) { g_hist[i] = 0; g_cur[i] = 0; }
    if (i < N_GRAPHS * H_DIM) g_sums[i] = 0.f;
    if (i < N_GRAPHS) g_cnt[i] = 0.f;
}

// ---------------- CSR build ----------------
__global__ void hist_kernel(const int* __restrict__ dst) {
    int e = blockIdx.x * blockDim.x + threadIdx.x;
    if (e < N_EDGES) atomicAdd(&g_hist[dst[e]], 1);
}

#define SCAN_T 1024
#define SCAN_CH 20   // 1024*20 >= 20000
__global__ __launch_bounds__(SCAN_T)
void scan_kernel() {
    __shared__ int sp[SCAN_T];
    int t = threadIdx.x;
    int start = t * SCAN_CH;
    int s = 0;
#pragma unroll
    for (int c = 0; c < SCAN_CH; c++) {
        int i = start + c;
        if (i < N_NODES) s += g_hist[i];
    }
    sp[t] = s;
    __syncthreads();
    for (int off = 1; off < SCAN_T; off <<= 1) {
        int v = (t >= off) ? sp[t - off] : 0;
        __syncthreads();
        sp[t] += v;
        __syncthreads();
    }
    int base = sp[t] - s;
#pragma unroll
    for (int c = 0; c < SCAN_CH; c++) {
        int i = start + c;
        if (i < N_NODES) { g_off[i] = base; base += g_hist[i]; }
    }
    for (int i = t; i < N_NODES; i += SCAN_T)
        g_dinv[i] = rsqrtf((float)g_hist[i] + 1.0f);
}

__global__ void fill_kernel(const int* __restrict__ src, const int* __restrict__ dst) {
    int e = blockIdx.x * blockDim.x + threadIdx.x;
    if (e >= N_EDGES) return;
    int d = dst[e];
    int pos = atomicAdd(&g_cur[d], 1);
    g_csr[g_off[d] + pos] = src[e];
}

// ---------------- tf32 MMA GEMM: U = (A@B) * dinv[row] --------------------
// 3-term split: D += Ahi*Bhi + Ahi*Blo + Alo*Bhi.
// Register-prefetch pipelined: next tile loads overlap MMA work.
#define BM 64
#define BN 64
#define BK 16
#define AP 20   // As pitch
#define BP 72   // Bs pitch

__device__ __forceinline__ uint32_t f2tf32(float x) {
    uint32_t r;
    asm("cvt.rna.tf32.f32 %0, %1;" : "=r"(r) : "f"(x));
    return r;
}
__device__ __forceinline__ void tf32_split(float x, uint32_t& hi, uint32_t& lo) {
    hi = f2tf32(x);
    float hf = __uint_as_float(hi);
    lo = f2tf32(x - hf);
}
__device__ __forceinline__ void mma_tf32(float* c, const uint32_t* a, const uint32_t* b) {
    asm volatile(
        "mma.sync.aligned.m16n8k8.row.col.f32.tf32.tf32.f32 "
        "{%0,%1,%2,%3},{%4,%5,%6,%7},{%8,%9},{%0,%1,%2,%3};"
        : "+f"(c[0]), "+f"(c[1]), "+f"(c[2]), "+f"(c[3])
        : "r"(a[0]), "r"(a[1]), "r"(a[2]), "r"(a[3]), "r"(b[0]), "r"(b[1]));
}

__global__ __launch_bounds__(128)
void gemm_tf32_rowscale_kernel(const float* __restrict__ A,
                               const float* __restrict__ B,
                               float* __restrict__ U,
                               int M, int K, int N) {
    __shared__ float As[BM][AP];
    __shared__ float Bs[BK][BP];
    const int bm   = blockIdx.y * BM;
    const int bn   = blockIdx.x * BN;
    const int tid  = threadIdx.x;
    const int wid  = tid >> 5;
    const int lane = tid & 31;
    const int wm   = wid >> 1;        // 0..1
    const int wn   = wid & 1;         // 0..1
    const int gid  = lane >> 2;       // 0..7
    const int tig  = lane & 3;        // 0..3

    // loader indices (2 float4 per thread per tile, for both A and B)
    const int ar0 = tid >> 2,            ac0 = (tid & 3) * 4;          // A part 0
    const int ar1 = (tid + 128) >> 2,    ac1 = (tid & 3) * 4;          // A part 1
    const int br0 = tid >> 4,            bc0 = (tid & 15) * 4;         // B part 0
    const int br1 = (tid + 128) >> 4,    bc1 = (tid & 15) * 4;         // B part 1

    float acc[2][4][4];
#pragma unroll
    for (int mt = 0; mt < 2; mt++)
#pragma unroll
        for (int nt = 0; nt < 4; nt++)
#pragma unroll
            for (int i = 0; i < 4; i++) acc[mt][nt][i] = 0.f;

    // ---- load tile 0 into regs, commit to smem ----
    float4 av0 = make_float4(0.f,0.f,0.f,0.f), av1 = make_float4(0.f,0.f,0.f,0.f);
    if (bm + ar0 < M) av0 = *reinterpret_cast<const float4*>(&A[(size_t)(bm + ar0) * K + ac0]);
    if (bm + ar1 < M) av1 = *reinterpret_cast<const float4*>(&A[(size_t)(bm + ar1) * K + ac1]);
    float4 bv0 = *reinterpret_cast<const float4*>(&B[(size_t)br0 * N + bn + bc0]);
    float4 bv1 = *reinterpret_cast<const float4*>(&B[(size_t)br1 * N + bn + bc1]);
    As[ar0][ac0+0]=av0.x; As[ar0][ac0+1]=av0.y; As[ar0][ac0+2]=av0.z; As[ar0][ac0+3]=av0.w;
    As[ar1][ac1+0]=av1.x; As[ar1][ac1+1]=av1.y; As[ar1][ac1+2]=av1.z; As[ar1][ac1+3]=av1.w;
    *reinterpret_cast<float4*>(&Bs[br0][bc0]) = bv0;
    *reinterpret_cast<float4*>(&Bs[br1][bc1]) = bv1;
    __syncthreads();

    for (int k0 = 0; k0 < K; k0 += BK) {
        const bool more = (k0 + BK < K);
        // prefetch next tile into registers while computing from smem
        if (more) {
            av0 = make_float4(0.f,0.f,0.f,0.f); av1 = make_float4(0.f,0.f,0.f,0.f);
            if (bm + ar0 < M) av0 = *reinterpret_cast<const float4*>(&A[(size_t)(bm + ar0) * K + k0 + BK + ac0]);
            if (bm + ar1 < M) av1 = *reinterpret_cast<const float4*>(&A[(size_t)(bm + ar1) * K + k0 + BK + ac1]);
            bv0 = *reinterpret_cast<const float4*>(&B[(size_t)(k0 + BK + br0) * N + bn + bc0]);
            bv1 = *reinterpret_cast<const float4*>(&B[(size_t)(k0 + BK + br1) * N + bn + bc1]);
        }

#pragma unroll
        for (int ks = 0; ks < BK; ks += 8) {
            uint32_t ahi[2][4], alo[2][4], bhi[4][2], blo[4][2];
#pragma unroll
            for (int mt = 0; mt < 2; mt++) {
                int r0 = wm * 32 + mt * 16 + gid;
                tf32_split(As[r0    ][ks + tig    ], ahi[mt][0], alo[mt][0]);
                tf32_split(As[r0 + 8][ks + tig    ], ahi[mt][1], alo[mt][1]);
                tf32_split(As[r0    ][ks + tig + 4], ahi[mt][2], alo[mt][2]);
                tf32_split(As[r0 + 8][ks + tig + 4], ahi[mt][3], alo[mt][3]);
            }
#pragma unroll
            for (int nt = 0; nt < 4; nt++) {
                int n = wn * 32 + nt * 8 + gid;
                tf32_split(Bs[ks + tig    ][n], bhi[nt][0], blo[nt][0]);
                tf32_split(Bs[ks + tig + 4][n], bhi[nt][1], blo[nt][1]);
            }
#pragma unroll
            for (int mt = 0; mt < 2; mt++)
#pragma unroll
                for (int nt = 0; nt < 4; nt++) {
                    mma_tf32(acc[mt][nt], ahi[mt], bhi[nt]);
                    mma_tf32(acc[mt][nt], ahi[mt], blo[nt]);
                    mma_tf32(acc[mt][nt], alo[mt], bhi[nt]);
                }
        }

        if (more) {
            __syncthreads();   // all warps done reading old tile
            As[ar0][ac0+0]=av0.x; As[ar0][ac0+1]=av0.y; As[ar0][ac0+2]=av0.z; As[ar0][ac0+3]=av0.w;
            As[ar1][ac1+0]=av1.x; As[ar1][ac1+1]=av1.y; As[ar1][ac1+2]=av1.z; As[ar1][ac1+3]=av1.w;
            *reinterpret_cast<float4*>(&Bs[br0][bc0]) = bv0;
            *reinterpret_cast<float4*>(&Bs[br1][bc1]) = bv1;
            __syncthreads();
        }
    }

    // epilogue: rowscale by dinv
#pragma unroll
    for (int mt = 0; mt < 2; mt++) {
        int r0 = bm + wm * 32 + mt * 16 + gid;
        int r1 = r0 + 8;
        float rs0 = (r0 < M) ? g_dinv[r0] : 0.f;
        float rs1 = (r1 < M) ? g_dinv[r1] : 0.f;
#pragma unroll
        for (int nt = 0; nt < 4; nt++) {
            int c = bn + wn * 32 + nt * 8 + tig * 2;
            if (r0 < M) {
                float2 v0 = make_float2(acc[mt][nt][0] * rs0, acc[mt][nt][1] * rs0);
                *reinterpret_cast<float2*>(&U[(size_t)r0 * N + c]) = v0;
            }
            if (r1 < M) {
                float2 v1 = make_float2(acc[mt][nt][2] * rs1, acc[mt][nt][3] * rs1);
                *reinterpret_cast<float2*>(&U[(size_t)r1 * N + c]) = v1;
            }
        }
    }
}

// ---------------- CSR gather conv: h[m] = relu(dinv[m]*(u[m]+Σu[s]) + b) ---
__global__ __launch_bounds__(64)
void gather_relu_kernel(const float* __restrict__ bias, float* __restrict__ out) {
    int m = blockIdx.x;
    int f4 = threadIdx.x;                  // 0..63
    const float4* U4 = reinterpret_cast<const float4*>(g_u);
    int beg = g_off[m];
    int cnt = g_hist[m];
    float4 acc = U4[(size_t)m * 64 + f4];  // self loop
    int e = 0;
    for (; e + 4 <= cnt; e += 4) {
        int s0 = g_csr[beg + e + 0], s1 = g_csr[beg + e + 1];
        int s2 = g_csr[beg + e + 2], s3 = g_csr[beg + e + 3];
        float4 v0 = U4[(size_t)s0 * 64 + f4];
        float4 v1 = U4[(size_t)s1 * 64 + f4];
        float4 v2 = U4[(size_t)s2 * 64 + f4];
        float4 v3 = U4[(size_t)s3 * 64 + f4];
        acc.x += (v0.x + v1.x) + (v2.x + v3.x);
        acc.y += (v0.y + v1.y) + (v2.y + v3.y);
        acc.z += (v0.z + v1.z) + (v2.z + v3.z);
        acc.w += (v0.w + v1.w) + (v2.w + v3.w);
    }
    for (; e < cnt; e++) {
        int s = g_csr[beg + e];
        float4 v = U4[(size_t)s * 64 + f4];
        acc.x += v.x; acc.y += v.y; acc.z += v.z; acc.w += v.w;
    }
    float di = g_dinv[m];
    float4 bb = reinterpret_cast<const float4*>(bias)[f4];
    float4 h;
    h.x = fmaxf(di * acc.x + bb.x, 0.f);
    h.y = fmaxf(di * acc.y + bb.y, 0.f);
    h.z = fmaxf(di * acc.z + bb.z, 0.f);
    h.w = fmaxf(di * acc.w + bb.w, 0.f);
    reinterpret_cast<float4*>(out)[(size_t)m * 64 + f4] = h;
}

// conv2 gather fused with mean-pool accumulation (h never materialized)
__global__ __launch_bounds__(64)
void gather_pool_kernel(const float* __restrict__ bias, const int* __restrict__ batch) {
    int m = blockIdx.x;
    int f4 = threadIdx.x;
    const float4* U4 = reinterpret_cast<const float4*>(g_u);
    int beg = g_off[m];
    int cnt = g_hist[m];
    float4 acc = U4[(size_t)m * 64 + f4];
    int e = 0;
    for (; e + 4 <= cnt; e += 4) {
        int s0 = g_csr[beg + e + 0], s1 = g_csr[beg + e + 1];
        int s2 = g_csr[beg + e + 2], s3 = g_csr[beg + e + 3];
        float4 v0 = U4[(size_t)s0 * 64 + f4];
        float4 v1 = U4[(size_t)s1 * 64 + f4];
        float4 v2 = U4[(size_t)s2 * 64 + f4];
        float4 v3 = U4[(size_t)s3 * 64 + f4];
        acc.x += (v0.x + v1.x) + (v2.x + v3.x);
        acc.y += (v0.y + v1.y) + (v2.y + v3.y);
        acc.z += (v0.z + v1.z) + (v2.z + v3.z);
        acc.w += (v0.w + v1.w) + (v2.w + v3.w);
    }
    for (; e < cnt; e++) {
        int s = g_csr[beg + e];
        float4 v = U4[(size_t)s * 64 + f4];
        acc.x += v.x; acc.y += v.y; acc.z += v.z; acc.w += v.w;
    }
    float di = g_dinv[m];
    float4 bb = reinterpret_cast<const float4*>(bias)[f4];
    float hx = fmaxf(di * acc.x + bb.x, 0.f);
    float hy = fmaxf(di * acc.y + bb.y, 0.f);
    float hz = fmaxf(di * acc.z + bb.z, 0.f);
    float hw = fmaxf(di * acc.w + bb.w, 0.f);
    int b = batch[m];
    float* sbase = &g_sums[(size_t)b * H_DIM + f4 * 4];
    atomicAdd(sbase + 0, hx);
    atomicAdd(sbase + 1, hy);
    atomicAdd(sbase + 2, hz);
    atomicAdd(sbase + 3, hw);
    if (f4 == 0) atomicAdd(&g_cnt[b], 1.0f);
}

__global__ void pool_div_kernel() {
    int g = blockIdx.x;
    int f = threadIdx.x;
    g_hg[g * H_DIM + f] = g_sums[g * H_DIM + f] / fmaxf(g_cnt[g], 1.0f);
}

// ---------------- mu / logvar / z ----------------
__global__ void muz_kernel(const float* __restrict__ Wmu, const float* __restrict__ bmu,
                           const float* __restrict__ Wlv, const float* __restrict__ blv,
                           const float* __restrict__ eps,
                           float* __restrict__ out_mu, float* __restrict__ out_lv) {
    int g = blockIdx.x;
    int l = threadIdx.x;            // 64
    __shared__ float sh[H_DIM];
    for (int k = l; k < H_DIM; k += L_DIM) sh[k] = g_hg[g * H_DIM + k];
    __syncthreads();
    float mu = bmu[l], lv = blv[l];
    for (int k = 0; k < H_DIM; k++) {
        float h = sh[k];
        mu += h * Wmu[k * L_DIM + l];
        lv += h * Wlv[k * L_DIM + l];
    }
    out_mu[g * L_DIM + l] = mu;
    out_lv[g * L_DIM + l] = lv;
    g_z[g * L_DIM + l] = mu + eps[g * L_DIM + l] * expf(0.5f * lv);
}

// ---------------- decoder dense+relu ----------------
__global__ void dense_relu_kernel(const float* __restrict__ X,
                                  const float* __restrict__ W,
                                  const float* __restrict__ b,
                                  float* __restrict__ Y, int K) {
    int g = blockIdx.x;
    int n = threadIdx.x;            // 256
    __shared__ float sx[H_DIM];
    if (n < K) sx[n] = X[g * K + n];
    __syncthreads();
    float acc = b[n];
    for (int k = 0; k < K; k++) acc += sx[k] * W[k * H_DIM + n];
    Y[g * H_DIM + n] = fmaxf(acc, 0.f);
}

// ---------------- adjacency decode ----------------
__global__ void pairmap_kernel() {
    int i = blockIdx.x;             // 0..99
    int j = threadIdx.x;            // 0..127
    if (j > i && j < MAXN) {
        int p = i * 99 - (i * (i - 1)) / 2 + (j - i - 1);
        g_pi[p] = i;
        g_pj[p] = j;
    }
}

__global__ void diag_kernel(float* __restrict__ adj) {
    int g = blockIdx.x;
    int i = threadIdx.x;
    if (i < MAXN)
        adj[(size_t)g * MAXN * MAXN + i * MAXN + i] = 0.f;
}

#define GCH 20
__global__ __launch_bounds__(128)
void adj_kernel(const float* __restrict__ D3, const float* __restrict__ db3,
                float* __restrict__ adj) {
    int p  = blockIdx.x * 128 + threadIdx.x;
    int g0 = blockIdx.y * GCH;
    __shared__ float sd2[GCH][H_DIM];
    for (int idx = threadIdx.x; idx < GCH * H_DIM; idx += 128)
        sd2[idx >> 8][idx & 255] = g_d2[(size_t)(g0 + (idx >> 8)) * H_DIM + (idx & 255)];
    __syncthreads();
    if (p >= NPAIR) return;
    int i = g_pi[p], j = g_pj[p];
    float bb = db3[p];
    float acc[GCH];
#pragma unroll
    for (int gg = 0; gg < GCH; gg++) acc[gg] = bb;
    for (int k = 0; k < H_DIM; k++) {
        float w = D3[(size_t)k * NPAIR + p];
#pragma unroll
        for (int gg = 0; gg < GCH; gg++) acc[gg] += sd2[gg][k] * w;
    }
#pragma unroll
    for (int gg = 0; gg < GCH; gg++) {
        float prob = 1.0f / (1.0f + expf(-acc[gg]));
        size_t base = (size_t)(g0 + gg) * (MAXN * MAXN);
        adj[base + i * MAXN + j] = prob;
        adj[base + j * MAXN + i] = prob;
    }
}

// ---------------- launch ----------------
extern "C" void kernel_launch(void* const* d_in, const int* in_sizes, int n_in,
                              void* d_out, int out_size) {
    const float* x    = (const float*)d_in[0];
    const int*   ei   = (const int*)  d_in[1];
    const int*   batch= (const int*)  d_in[2];
    const float* eps  = (const float*)d_in[3];
    const float* W1   = (const float*)d_in[4];
    const float* b1   = (const float*)d_in[5];
    const float* W2   = (const float*)d_in[6];
    const float* b2   = (const float*)d_in[7];
    const float* Wmu  = (const float*)d_in[8];
    const float* bmu  = (const float*)d_in[9];
    const float* Wlv  = (const float*)d_in[10];
    const float* blv  = (const float*)d_in[11];
    const float* D1   = (const float*)d_in[12];
    const float* db1  = (const float*)d_in[13];
    const float* D2   = (const float*)d_in[14];
    const float* db2  = (const float*)d_in[15];
    const float* D3   = (const float*)d_in[16];
    const float* db3  = (const float*)d_in[17];

    const int* src = ei;
    const int* dst = ei + N_EDGES;

    float* out      = (float*)d_out;
    float* out_adj  = out;                                        // 200*100*100
    float* out_mu   = out + (size_t)N_GRAPHS * MAXN * MAXN;       // 200*64
    float* out_lv   = out_mu + (size_t)N_GRAPHS * L_DIM;          // 200*64

    float *p_u, *p_h, *p_z, *p_d1, *p_d2;
    cudaGetSymbolAddress((void**)&p_u,  g_u);
    cudaGetSymbolAddress((void**)&p_h,  g_h);
    cudaGetSymbolAddress((void**)&p_z,  g_z);
    cudaGetSymbolAddress((void**)&p_d1, g_d1);
    cudaGetSymbolAddress((void**)&p_d2, g_d2);

    // Lazy-created side stream + events (first call is the uncaptured
    // correctness run; capture reuses them — no creation under capture).
    static cudaStream_t s_side = nullptr;
    static cudaEvent_t  ev_fork = nullptr, ev_join = nullptr;
    if (s_side == nullptr) {
        cudaStreamCreateWithFlags(&s_side, cudaStreamNonBlocking);
        cudaEventCreateWithFlags(&ev_fork, cudaEventDisableTiming);
        cudaEventCreateWithFlags(&ev_join, cudaEventDisableTiming);
    }

    // CSR prefix (dinv needed by gemm1 epilogue) on main stream
    zero_kernel<<<(N_GRAPHS * H_DIM + 255) / 256, 256>>>();
    hist_kernel<<<(N_EDGES + 255) / 256, 256>>>(dst);
    scan_kernel<<<1, SCAN_T>>>();

    // fork: fill + pairmap + diag run concurrently with gemm1
    cudaEventRecord(ev_fork, 0);
    cudaStreamWaitEvent(s_side, ev_fork, 0);
    fill_kernel<<<(N_EDGES + 255) / 256, 256, 0, s_side>>>(src, dst);
    pairmap_kernel<<<MAXN, 128, 0, s_side>>>();
    diag_kernel<<<N_GRAPHS, 128, 0, s_side>>>(out_adj);
    cudaEventRecord(ev_join, s_side);

    dim3 ggrid(H_DIM / BN, (N_NODES + BM - 1) / BM);

    // conv1 gemm (needs only dinv) overlaps the side stream
    gemm_tf32_rowscale_kernel<<<ggrid, 128>>>(x, W1, p_u, N_NODES, IN_DIM, H_DIM);

    // join: gather needs the CSR fill
    cudaStreamWaitEvent(0, ev_join, 0);
    gather_relu_kernel<<<N_NODES, 64>>>(b1, p_h);

    // conv2: gemm -> gather fused with mean-pool accumulation
    gemm_tf32_rowscale_kernel<<<ggrid, 128>>>(p_h, W2, p_u, N_NODES, H_DIM, H_DIM);
    gather_pool_kernel<<<N_NODES, 64>>>(b2, batch);
    pool_div_kernel<<<N_GRAPHS, H_DIM>>>();

    // VAE head
    muz_kernel<<<N_GRAPHS, L_DIM>>>(Wmu, bmu, Wlv, blv, eps, out_mu, out_lv);

    // decoder MLP
    dense_relu_kernel<<<N_GRAPHS, H_DIM>>>(p_z,  D1, db1, p_d1, L_DIM);
    dense_relu_kernel<<<N_GRAPHS, H_DIM>>>(p_d1, D2, db2, p_d2, H_DIM);

    // adjacency
    adj_kernel<<<dim3((NPAIR + 127) / 128, N_GRAPHS / GCH), 128>>>(D3, db3, out_adj);
}

// round 15
// speedup vs baseline: 1.0286x; 1.0286x over previous
#include <cuda_runtime.h>
#include <cstdint>
#include <cmath>

// ---------------- problem constants ----------------
#define N_NODES   20000
#define N_EDGES   320000
#define N_GRAPHS  200
#define MAXN      100
#define NPAIR     4950          // 100*99/2
#define IN_DIM    128
#define H_DIM     256
#define L_DIM     64

// ---------------- scratch (device globals; no allocation allowed) ----------
__device__ __align__(128) int   g_hist[N_NODES];            // in-degree
__device__ __align__(128) int   g_off [N_NODES];            // CSR exclusive offsets
__device__ __align__(128) int   g_cur [N_NODES];            // fill cursors
__device__ __align__(128) int   g_csr [N_EDGES];            // src ids grouped by dst
__device__ __align__(128) float g_dinv[N_NODES];            // rsqrt(deg+1)
__device__ __align__(128) float g_u   [N_NODES * H_DIM];    // (A@W)*dinv[row]
__device__ __align__(128) float g_h   [N_NODES * H_DIM];    // conv1 output
__device__ __align__(128) float g_sums[N_GRAPHS * H_DIM];
__device__ __align__(128) float g_cnt [N_GRAPHS];
__device__ __align__(128) float g_hg  [N_GRAPHS * H_DIM];
__device__ __align__(128) float g_z   [N_GRAPHS * L_DIM];
__device__ __align__(128) float g_d1  [N_GRAPHS * H_DIM];
__device__ __align__(128) float g_d2  [N_GRAPHS * H_DIM];
__device__ __align__(128) int   g_pi  [NPAIR];
__device__ __align__(128) int   g_pj  [NPAIR];

// ---------------- zero scratch ----------------
__global__ void zero_kernel() {
    int i = blockIdx.x * blockDim.x + threadIdx.x;
    if (i < N_NODES) { g_hist[i] = 0; g_cur[i] = 0; }
    if (i < N_GRAPHS * H_DIM) g_sums[i] = 0.f;
    if (i < N_GRAPHS) g_cnt[i] = 0.f;
}

// ---------------- CSR build ----------------
__global__ void hist_kernel(const int* __restrict__ dst) {
    int e = blockIdx.x * blockDim.x + threadIdx.x;
    if (e < N_EDGES) atomicAdd(&g_hist[dst[e]], 1);
}

#define SCAN_T 1024
#define SCAN_CH 20   // 1024*20 >= 20000
__global__ __launch_bounds__(SCAN_T)
void scan_kernel() {
    __shared__ int sp[SCAN_T];
    int t = threadIdx.x;
    int start = t * SCAN_CH;
    int s = 0;
#pragma unroll
    for (int c = 0; c < SCAN_CH; c++) {
        int i = start + c;
        if (i < N_NODES) s += g_hist[i];
    }
    sp[t] = s;
    __syncthreads();
    for (int off = 1; off < SCAN_T; off <<= 1) {
        int v = (t >= off) ? sp[t - off] : 0;
        __syncthreads();
        sp[t] += v;
        __syncthreads();
    }
    int base = sp[t] - s;
#pragma unroll
    for (int c = 0; c < SCAN_CH; c++) {
        int i = start + c;
        if (i < N_NODES) { g_off[i] = base; base += g_hist[i]; }
    }
    for (int i = t; i < N_NODES; i += SCAN_T)
        g_dinv[i] = rsqrtf((float)g_hist[i] + 1.0f);
}

__global__ void fill_kernel(const int* __restrict__ src, const int* __restrict__ dst) {
    int e = blockIdx.x * blockDim.x + threadIdx.x;
    if (e >= N_EDGES) return;
    int d = dst[e];
    int pos = atomicAdd(&g_cur[d], 1);
    g_csr[g_off[d] + pos] = src[e];
}

// ---------------- tf32 MMA GEMM: U = (A@B) * dinv[row] --------------------
// 3-term split for fp32-class accuracy: D += Ahi*Bhi + Ahi*Blo + Alo*Bhi
#define BM 64
#define BN 64
#define BK 16
#define AP 20   // As pitch (conflict-free for A-fragment loads)
#define BP 72   // Bs pitch (conflict-free for B-fragment loads)

__device__ __forceinline__ uint32_t f2tf32(float x) {
    uint32_t r;
    asm("cvt.rna.tf32.f32 %0, %1;" : "=r"(r) : "f"(x));
    return r;
}
__device__ __forceinline__ void tf32_split(float x, uint32_t& hi, uint32_t& lo) {
    hi = f2tf32(x);
    float hf = __uint_as_float(hi);
    lo = f2tf32(x - hf);
}
__device__ __forceinline__ void mma_tf32(float* c, const uint32_t* a, const uint32_t* b) {
    asm volatile(
        "mma.sync.aligned.m16n8k8.row.col.f32.tf32.tf32.f32 "
        "{%0,%1,%2,%3},{%4,%5,%6,%7},{%8,%9},{%0,%1,%2,%3};"
        : "+f"(c[0]), "+f"(c[1]), "+f"(c[2]), "+f"(c[3])
        : "r"(a[0]), "r"(a[1]), "r"(a[2]), "r"(a[3]), "r"(b[0]), "r"(b[1]));
}

__global__ __launch_bounds__(128)
void gemm_tf32_rowscale_kernel(const float* __restrict__ A,
                               const float* __restrict__ B,
                               float* __restrict__ U,
                               int M, int K, int N) {
    __shared__ float As[BM][AP];
    __shared__ float Bs[BK][BP];
    const int bm   = blockIdx.y * BM;
    const int bn   = blockIdx.x * BN;
    const int tid  = threadIdx.x;
    const int wid  = tid >> 5;
    const int lane = tid & 31;
    const int wm   = wid >> 1;        // 0..1
    const int wn   = wid & 1;         // 0..1
    const int gid  = lane >> 2;       // 0..7
    const int tig  = lane & 3;        // 0..3

    float acc[2][4][4];
#pragma unroll
    for (int mt = 0; mt < 2; mt++)
#pragma unroll
        for (int nt = 0; nt < 4; nt++)
#pragma unroll
            for (int i = 0; i < 4; i++) acc[mt][nt][i] = 0.f;

    for (int k0 = 0; k0 < K; k0 += BK) {
        // A tile 64x16 (row-major slice)
#pragma unroll
        for (int l = 0; l < 2; l++) {
            int t = tid + l * 128;
            int r = t >> 2;
            int c = (t & 3) * 4;
            float4 v = make_float4(0.f, 0.f, 0.f, 0.f);
            if (bm + r < M)
                v = *reinterpret_cast<const float4*>(&A[(size_t)(bm + r) * K + k0 + c]);
            As[r][c + 0] = v.x; As[r][c + 1] = v.y;
            As[r][c + 2] = v.z; As[r][c + 3] = v.w;
        }
        // B tile 16x64
#pragma unroll
        for (int l = 0; l < 2; l++) {
            int t = tid + l * 128;
            int r = t >> 4;
            int c = (t & 15) * 4;
            float4 v = *reinterpret_cast<const float4*>(&B[(size_t)(k0 + r) * N + bn + c]);
            *reinterpret_cast<float4*>(&Bs[r][c]) = v;
        }
        __syncthreads();

#pragma unroll
        for (int ks = 0; ks < BK; ks += 8) {
            uint32_t ahi[2][4], alo[2][4], bhi[4][2], blo[4][2];
#pragma unroll
            for (int mt = 0; mt < 2; mt++) {
                int r0 = wm * 32 + mt * 16 + gid;
                tf32_split(As[r0    ][ks + tig    ], ahi[mt][0], alo[mt][0]);
                tf32_split(As[r0 + 8][ks + tig    ], ahi[mt][1], alo[mt][1]);
                tf32_split(As[r0    ][ks + tig + 4], ahi[mt][2], alo[mt][2]);
                tf32_split(As[r0 + 8][ks + tig + 4], ahi[mt][3], alo[mt][3]);
            }
#pragma unroll
            for (int nt = 0; nt < 4; nt++) {
                int n = wn * 32 + nt * 8 + gid;
                tf32_split(Bs[ks + tig    ][n], bhi[nt][0], blo[nt][0]);
                tf32_split(Bs[ks + tig + 4][n], bhi[nt][1], blo[nt][1]);
            }
#pragma unroll
            for (int mt = 0; mt < 2; mt++)
#pragma unroll
                for (int nt = 0; nt < 4; nt++) {
                    mma_tf32(acc[mt][nt], ahi[mt], bhi[nt]);
                    mma_tf32(acc[mt][nt], ahi[mt], blo[nt]);
                    mma_tf32(acc[mt][nt], alo[mt], bhi[nt]);
                }
        }
        __syncthreads();
    }

    // epilogue: rowscale by dinv, fragment layout c0/c1 = (row, 2*tig(+1)), c2/c3 = row+8
#pragma unroll
    for (int mt = 0; mt < 2; mt++) {
        int r0 = bm + wm * 32 + mt * 16 + gid;
        int r1 = r0 + 8;
        float rs0 = (r0 < M) ? g_dinv[r0] : 0.f;
        float rs1 = (r1 < M) ? g_dinv[r1] : 0.f;
#pragma unroll
        for (int nt = 0; nt < 4; nt++) {
            int c = bn + wn * 32 + nt * 8 + tig * 2;
            if (r0 < M) {
                float2 v0 = make_float2(acc[mt][nt][0] * rs0, acc[mt][nt][1] * rs0);
                *reinterpret_cast<float2*>(&U[(size_t)r0 * N + c]) = v0;
            }
            if (r1 < M) {
                float2 v1 = make_float2(acc[mt][nt][2] * rs1, acc[mt][nt][3] * rs1);
                *reinterpret_cast<float2*>(&U[(size_t)r1 * N + c]) = v1;
            }
        }
    }
}

// ---------------- CSR gather conv: h[m] = relu(dinv[m]*(u[m]+Σu[s]) + b) ---
__global__ __launch_bounds__(64)
void gather_relu_kernel(const float* __restrict__ bias, float* __restrict__ out) {
    int m = blockIdx.x;
    int f4 = threadIdx.x;                  // 0..63
    const float4* U4 = reinterpret_cast<const float4*>(g_u);
    int beg = g_off[m];
    int cnt = g_hist[m];
    float4 acc = U4[(size_t)m * 64 + f4];  // self loop
    int e = 0;
    for (; e + 4 <= cnt; e += 4) {
        int s0 = g_csr[beg + e + 0], s1 = g_csr[beg + e + 1];
        int s2 = g_csr[beg + e + 2], s3 = g_csr[beg + e + 3];
        float4 v0 = U4[(size_t)s0 * 64 + f4];
        float4 v1 = U4[(size_t)s1 * 64 + f4];
        float4 v2 = U4[(size_t)s2 * 64 + f4];
        float4 v3 = U4[(size_t)s3 * 64 + f4];
        acc.x += (v0.x + v1.x) + (v2.x + v3.x);
        acc.y += (v0.y + v1.y) + (v2.y + v3.y);
        acc.z += (v0.z + v1.z) + (v2.z + v3.z);
        acc.w += (v0.w + v1.w) + (v2.w + v3.w);
    }
    for (; e < cnt; e++) {
        int s = g_csr[beg + e];
        float4 v = U4[(size_t)s * 64 + f4];
        acc.x += v.x; acc.y += v.y; acc.z += v.z; acc.w += v.w;
    }
    float di = g_dinv[m];
    float4 bb = reinterpret_cast<const float4*>(bias)[f4];
    float4 h;
    h.x = fmaxf(di * acc.x + bb.x, 0.f);
    h.y = fmaxf(di * acc.y + bb.y, 0.f);
    h.z = fmaxf(di * acc.z + bb.z, 0.f);
    h.w = fmaxf(di * acc.w + bb.w, 0.f);
    reinterpret_cast<float4*>(out)[(size_t)m * 64 + f4] = h;
}

// conv2 gather fused with mean-pool accumulation (h never materialized)
__global__ __launch_bounds__(64)
void gather_pool_kernel(const float* __restrict__ bias, const int* __restrict__ batch) {
    int m = blockIdx.x;
    int f4 = threadIdx.x;
    const float4* U4 = reinterpret_cast<const float4*>(g_u);
    int beg = g_off[m];
    int cnt = g_hist[m];
    float4 acc = U4[(size_t)m * 64 + f4];
    int e = 0;
    for (; e + 4 <= cnt; e += 4) {
        int s0 = g_csr[beg + e + 0], s1 = g_csr[beg + e + 1];
        int s2 = g_csr[beg + e + 2], s3 = g_csr[beg + e + 3];
        float4 v0 = U4[(size_t)s0 * 64 + f4];
        float4 v1 = U4[(size_t)s1 * 64 + f4];
        float4 v2 = U4[(size_t)s2 * 64 + f4];
        float4 v3 = U4[(size_t)s3 * 64 + f4];
        acc.x += (v0.x + v1.x) + (v2.x + v3.x);
        acc.y += (v0.y + v1.y) + (v2.y + v3.y);
        acc.z += (v0.z + v1.z) + (v2.z + v3.z);
        acc.w += (v0.w + v1.w) + (v2.w + v3.w);
    }
    for (; e < cnt; e++) {
        int s = g_csr[beg + e];
        float4 v = U4[(size_t)s * 64 + f4];
        acc.x += v.x; acc.y += v.y; acc.z += v.z; acc.w += v.w;
    }
    float di = g_dinv[m];
    float4 bb = reinterpret_cast<const float4*>(bias)[f4];
    float hx = fmaxf(di * acc.x + bb.x, 0.f);
    float hy = fmaxf(di * acc.y + bb.y, 0.f);
    float hz = fmaxf(di * acc.z + bb.z, 0.f);
    float hw = fmaxf(di * acc.w + bb.w, 0.f);
    int b = batch[m];
    float* sbase = &g_sums[(size_t)b * H_DIM + f4 * 4];
    atomicAdd(sbase + 0, hx);
    atomicAdd(sbase + 1, hy);
    atomicAdd(sbase + 2, hz);
    atomicAdd(sbase + 3, hw);
    if (f4 == 0) atomicAdd(&g_cnt[b], 1.0f);
}

__global__ void pool_div_kernel() {
    int g = blockIdx.x;
    int f = threadIdx.x;
    g_hg[g * H_DIM + f] = g_sums[g * H_DIM + f] / fmaxf(g_cnt[g], 1.0f);
}

// ---------------- mu / logvar / z ----------------
__global__ void muz_kernel(const float* __restrict__ Wmu, const float* __restrict__ bmu,
                           const float* __restrict__ Wlv, const float* __restrict__ blv,
                           const float* __restrict__ eps,
                           float* __restrict__ out_mu, float* __restrict__ out_lv) {
    int g = blockIdx.x;
    int l = threadIdx.x;            // 64
    __shared__ float sh[H_DIM];
    for (int k = l; k < H_DIM; k += L_DIM) sh[k] = g_hg[g * H_DIM + k];
    __syncthreads();
    float mu = bmu[l], lv = blv[l];
    for (int k = 0; k < H_DIM; k++) {
        float h = sh[k];
        mu += h * Wmu[k * L_DIM + l];
        lv += h * Wlv[k * L_DIM + l];
    }
    out_mu[g * L_DIM + l] = mu;
    out_lv[g * L_DIM + l] = lv;
    g_z[g * L_DIM + l] = mu + eps[g * L_DIM + l] * expf(0.5f * lv);
}

// ---------------- decoder dense+relu ----------------
__global__ void dense_relu_kernel(const float* __restrict__ X,
                                  const float* __restrict__ W,
                                  const float* __restrict__ b,
                                  float* __restrict__ Y, int K) {
    int g = blockIdx.x;
    int n = threadIdx.x;            // 256
    __shared__ float sx[H_DIM];
    if (n < K) sx[n] = X[g * K + n];
    __syncthreads();
    float acc = b[n];
    for (int k = 0; k < K; k++) acc += sx[k] * W[k * H_DIM + n];
    Y[g * H_DIM + n] = fmaxf(acc, 0.f);
}

// ---------------- adjacency decode ----------------
__global__ void pairmap_kernel() {
    int i = blockIdx.x;             // 0..99
    int j = threadIdx.x;            // 0..127
    if (j > i && j < MAXN) {
        int p = i * 99 - (i * (i - 1)) / 2 + (j - i - 1);
        g_pi[p] = i;
        g_pj[p] = j;
    }
}

__global__ void diag_kernel(float* __restrict__ adj) {
    int g = blockIdx.x;
    int i = threadIdx.x;
    if (i < MAXN)
        adj[(size_t)g * MAXN * MAXN + i * MAXN + i] = 0.f;
}

#define GCH 20
__global__ __launch_bounds__(128)
void adj_kernel(const float* __restrict__ D3, const float* __restrict__ db3,
                float* __restrict__ adj) {
    int p  = blockIdx.x * 128 + threadIdx.x;
    int g0 = blockIdx.y * GCH;
    __shared__ float sd2[GCH][H_DIM];
    for (int idx = threadIdx.x; idx < GCH * H_DIM; idx += 128)
        sd2[idx >> 8][idx & 255] = g_d2[(size_t)(g0 + (idx >> 8)) * H_DIM + (idx & 255)];
    __syncthreads();
    if (p >= NPAIR) return;
    int i = g_pi[p], j = g_pj[p];
    float bb = db3[p];
    float acc[GCH];
#pragma unroll
    for (int gg = 0; gg < GCH; gg++) acc[gg] = bb;
    for (int k = 0; k < H_DIM; k++) {
        float w = D3[(size_t)k * NPAIR + p];
#pragma unroll
        for (int gg = 0; gg < GCH; gg++) acc[gg] += sd2[gg][k] * w;
    }
#pragma unroll
    for (int gg = 0; gg < GCH; gg++) {
        float prob = 1.0f / (1.0f + expf(-acc[gg]));
        size_t base = (size_t)(g0 + gg) * (MAXN * MAXN);
        adj[base + i * MAXN + j] = prob;
        adj[base + j * MAXN + i] = prob;
    }
}

// ---------------- launch ----------------
extern "C" void kernel_launch(void* const* d_in, const int* in_sizes, int n_in,
                              void* d_out, int out_size) {
    const float* x    = (const float*)d_in[0];
    const int*   ei   = (const int*)  d_in[1];
    const int*   batch= (const int*)  d_in[2];
    const float* eps  = (const float*)d_in[3];
    const float* W1   = (const float*)d_in[4];
    const float* b1   = (const float*)d_in[5];
    const float* W2   = (const float*)d_in[6];
    const float* b2   = (const float*)d_in[7];
    const float* Wmu  = (const float*)d_in[8];
    const float* bmu  = (const float*)d_in[9];
    const float* Wlv  = (const float*)d_in[10];
    const float* blv  = (const float*)d_in[11];
    const float* D1   = (const float*)d_in[12];
    const float* db1  = (const float*)d_in[13];
    const float* D2   = (const float*)d_in[14];
    const float* db2  = (const float*)d_in[15];
    const float* D3   = (const float*)d_in[16];
    const float* db3  = (const float*)d_in[17];

    const int* src = ei;
    const int* dst = ei + N_EDGES;

    float* out      = (float*)d_out;
    float* out_adj  = out;                                        // 200*100*100
    float* out_mu   = out + (size_t)N_GRAPHS * MAXN * MAXN;       // 200*64
    float* out_lv   = out_mu + (size_t)N_GRAPHS * L_DIM;          // 200*64

    float *p_u, *p_h, *p_z, *p_d1, *p_d2;
    cudaGetSymbolAddress((void**)&p_u,  g_u);
    cudaGetSymbolAddress((void**)&p_h,  g_h);
    cudaGetSymbolAddress((void**)&p_z,  g_z);
    cudaGetSymbolAddress((void**)&p_d1, g_d1);
    cudaGetSymbolAddress((void**)&p_d2, g_d2);

    // Lazy-created side stream + events (first call is the uncaptured
    // correctness run; capture reuses them — no creation under capture).
    static cudaStream_t s_side = nullptr;
    static cudaEvent_t  ev_fork = nullptr, ev_join = nullptr;
    if (s_side == nullptr) {
        cudaStreamCreateWithFlags(&s_side, cudaStreamNonBlocking);
        cudaEventCreateWithFlags(&ev_fork, cudaEventDisableTiming);
        cudaEventCreateWithFlags(&ev_join, cudaEventDisableTiming);
    }

    // CSR prefix (dinv needed by gemm1 epilogue) on main stream
    zero_kernel<<<(N_GRAPHS * H_DIM + 255) / 256, 256>>>();
    hist_kernel<<<(N_EDGES + 255) / 256, 256>>>(dst);
    scan_kernel<<<1, SCAN_T>>>();

    // fork: fill + pairmap + diag run concurrently with gemm1
    cudaEventRecord(ev_fork, 0);
    cudaStreamWaitEvent(s_side, ev_fork, 0);
    fill_kernel<<<(N_EDGES + 255) / 256, 256, 0, s_side>>>(src, dst);
    pairmap_kernel<<<MAXN, 128, 0, s_side>>>();
    diag_kernel<<<N_GRAPHS, 128, 0, s_side>>>(out_adj);
    cudaEventRecord(ev_join, s_side);

    dim3 ggrid(H_DIM / BN, (N_NODES + BM - 1) / BM);

    // conv1 gemm (needs only dinv) overlaps the side stream
    gemm_tf32_rowscale_kernel<<<ggrid, 128>>>(x, W1, p_u, N_NODES, IN_DIM, H_DIM);

    // join: gather needs the CSR fill
    cudaStreamWaitEvent(0, ev_join, 0);
    gather_relu_kernel<<<N_NODES, 64>>>(b1, p_h);

    // conv2: gemm -> gather fused with mean-pool accumulation
    gemm_tf32_rowscale_kernel<<<ggrid, 128>>>(p_h, W2, p_u, N_NODES, H_DIM, H_DIM);
    gather_pool_kernel<<<N_NODES, 64>>>(b2, batch);
    pool_div_kernel<<<N_GRAPHS, H_DIM>>>();

    // VAE head
    muz_kernel<<<N_GRAPHS, L_DIM>>>(Wmu, bmu, Wlv, blv, eps, out_mu, out_lv);

    // decoder MLP
    dense_relu_kernel<<<N_GRAPHS, H_DIM>>>(p_z,  D1, db1, p_d1, L_DIM);
    dense_relu_kernel<<<N_GRAPHS, H_DIM>>>(p_d1, D2, db2, p_d2, H_DIM);

    // adjacency
    adj_kernel<<<dim3((NPAIR + 127) / 128, N_GRAPHS / GCH), 128>>>(D3, db3, out_adj);
}

// round 16
// speedup vs baseline: 1.1211x; 1.0899x over previous
#include <cuda_runtime.h>
#include <cstdint>
#include <cmath>

// ---------------- problem constants ----------------
#define N_NODES   20000
#define N_EDGES   320000
#define N_GRAPHS  200
#define MAXN      100
#define NPAIR     4950          // 100*99/2
#define IN_DIM    128
#define H_DIM     256
#define L_DIM     64

// ---------------- scratch (device globals; no allocation allowed) ----------
__device__ __align__(128) int   g_hist[N_NODES];            // in-degree
__device__ __align__(128) int   g_off [N_NODES];            // CSR exclusive offsets
__device__ __align__(128) int   g_cur [N_NODES];            // fill cursors
__device__ __align__(128) int   g_csr [N_EDGES];            // src ids grouped by dst
__device__ __align__(128) float g_dinv[N_NODES];            // rsqrt(deg+1)
__device__ __align__(128) float g_u   [N_NODES * H_DIM];    // (A@W)*dinv[row]
__device__ __align__(128) float g_h   [N_NODES * H_DIM];    // conv1 output
__device__ __align__(128) float g_sums[N_GRAPHS * H_DIM];
__device__ __align__(128) float g_cnt [N_GRAPHS];
__device__ __align__(128) float g_hg  [N_GRAPHS * H_DIM];
__device__ __align__(128) float g_z   [N_GRAPHS * L_DIM];
__device__ __align__(128) float g_d1  [N_GRAPHS * H_DIM];
__device__ __align__(128) float g_d2  [N_GRAPHS * H_DIM];
__device__ __align__(128) int   g_pi  [NPAIR];
__device__ __align__(128) int   g_pj  [NPAIR];

// ---------------- zero scratch ----------------
__global__ void zero_kernel() {
    int i = blockIdx.x * blockDim.x + threadIdx.x;
    if (i < N_NODES) { g_hist[i] = 0; g_cur[i] = 0; }
    if (i < N_GRAPHS * H_DIM) g_sums[i] = 0.f;
    if (i < N_GRAPHS) g_cnt[i] = 0.f;
}

// ---------------- CSR build ----------------
__global__ void hist_kernel(const int* __restrict__ dst) {
    int e = blockIdx.x * blockDim.x + threadIdx.x;
    if (e < N_EDGES) atomicAdd(&g_hist[dst[e]], 1);
}

#define SCAN_T 1024
#define SCAN_CH 20   // 1024*20 >= 20000
__global__ __launch_bounds__(SCAN_T)
void scan_kernel() {
    __shared__ int sp[SCAN_T];
    int t = threadIdx.x;
    int start = t * SCAN_CH;
    int s = 0;
#pragma unroll
    for (int c = 0; c < SCAN_CH; c++) {
        int i = start + c;
        if (i < N_NODES) s += g_hist[i];
    }
    sp[t] = s;
    __syncthreads();
    for (int off = 1; off < SCAN_T; off <<= 1) {
        int v = (t >= off) ? sp[t - off] : 0;
        __syncthreads();
        sp[t] += v;
        __syncthreads();
    }
    int base = sp[t] - s;
#pragma unroll
    for (int c = 0; c < SCAN_CH; c++) {
        int i = start + c;
        if (i < N_NODES) { g_off[i] = base; base += g_hist[i]; }
    }
    for (int i = t; i < N_NODES; i += SCAN_T)
        g_dinv[i] = rsqrtf((float)g_hist[i] + 1.0f);
}

__global__ void fill_kernel(const int* __restrict__ src, const int* __restrict__ dst) {
    int e = blockIdx.x * blockDim.x + threadIdx.x;
    if (e >= N_EDGES) return;
    int d = dst[e];
    int pos = atomicAdd(&g_cur[d], 1);
    g_csr[g_off[d] + pos] = src[e];
}

// ---------------- tf32 MMA GEMM: U = (A@B) * dinv[row] --------------------
// 3-term split: D += Ahi*Bhi + Ahi*Blo + Alo*Bhi.
// cp.async double-buffered smem pipeline (no register prefetch pressure).
#define BM 64
#define BN 64
#define BK 16
#define AP 20   // As pitch (conflict-free for A-fragment loads)
#define BP 72   // Bs pitch (conflict-free for B-fragment loads)

__device__ __forceinline__ uint32_t f2tf32(float x) {
    uint32_t r;
    asm("cvt.rna.tf32.f32 %0, %1;" : "=r"(r) : "f"(x));
    return r;
}
__device__ __forceinline__ void tf32_split(float x, uint32_t& hi, uint32_t& lo) {
    hi = f2tf32(x);
    float hf = __uint_as_float(hi);
    lo = f2tf32(x - hf);
}
__device__ __forceinline__ void mma_tf32(float* c, const uint32_t* a, const uint32_t* b) {
    asm volatile(
        "mma.sync.aligned.m16n8k8.row.col.f32.tf32.tf32.f32 "
        "{%0,%1,%2,%3},{%4,%5,%6,%7},{%8,%9},{%0,%1,%2,%3};"
        : "+f"(c[0]), "+f"(c[1]), "+f"(c[2]), "+f"(c[3])
        : "r"(a[0]), "r"(a[1]), "r"(a[2]), "r"(a[3]), "r"(b[0]), "r"(b[1]));
}
__device__ __forceinline__ void cp_async16(uint32_t saddr, const void* g, int src_sz) {
    asm volatile("cp.async.ca.shared.global [%0], [%1], 16, %2;\n"
                 :: "r"(saddr), "l"(g), "r"(src_sz));
}

__global__ __launch_bounds__(128)
void gemm_tf32_rowscale_kernel(const float* __restrict__ A,
                               const float* __restrict__ B,
                               float* __restrict__ U,
                               int M, int K, int N) {
    __shared__ float As[2][BM][AP];
    __shared__ float Bs[2][BK][BP];
    const int bm   = blockIdx.y * BM;
    const int bn   = blockIdx.x * BN;
    const int tid  = threadIdx.x;
    const int wid  = tid >> 5;
    const int lane = tid & 31;
    const int wm   = wid >> 1;        // 0..1
    const int wn   = wid & 1;         // 0..1
    const int gid  = lane >> 2;       // 0..7
    const int tig  = lane & 3;        // 0..3

    // loader indices: 2 x 16B per thread for each of A and B
    const int ar0 = tid >> 2,         ac = (tid & 3) * 4;
    const int ar1 = (tid + 128) >> 2;
    const int br0 = tid >> 4,         bc = (tid & 15) * 4;
    const int br1 = (tid + 128) >> 4;
    // clamped A rows (OOB lanes use src_size=0 zero-fill; address stays valid)
    const int am0 = (bm + ar0 < M) ? (bm + ar0) : (M - 1);
    const int am1 = (bm + ar1 < M) ? (bm + ar1) : (M - 1);
    const int az0 = (bm + ar0 < M) ? 16 : 0;
    const int az1 = (bm + ar1 < M) ? 16 : 0;

    float acc[2][4][4];
#pragma unroll
    for (int mt = 0; mt < 2; mt++)
#pragma unroll
        for (int nt = 0; nt < 4; nt++)
#pragma unroll
            for (int i = 0; i < 4; i++) acc[mt][nt][i] = 0.f;

    // issue tile 0
    {
        cp_async16((uint32_t)__cvta_generic_to_shared(&As[0][ar0][ac]),
                   &A[(size_t)am0 * K + ac], az0);
        cp_async16((uint32_t)__cvta_generic_to_shared(&As[0][ar1][ac]),
                   &A[(size_t)am1 * K + ac], az1);
        cp_async16((uint32_t)__cvta_generic_to_shared(&Bs[0][br0][bc]),
                   &B[(size_t)br0 * N + bn + bc], 16);
        cp_async16((uint32_t)__cvta_generic_to_shared(&Bs[0][br1][bc]),
                   &B[(size_t)br1 * N + bn + bc], 16);
        asm volatile("cp.async.commit_group;\n");
    }
    asm volatile("cp.async.wait_group 0;\n");
    __syncthreads();

    int buf = 0;
    for (int k0 = 0; k0 < K; k0 += BK) {
        const bool more = (k0 + BK < K);
        if (more) {
            int nb = buf ^ 1;
            cp_async16((uint32_t)__cvta_generic_to_shared(&As[nb][ar0][ac]),
                       &A[(size_t)am0 * K + k0 + BK + ac], az0);
            cp_async16((uint32_t)__cvta_generic_to_shared(&As[nb][ar1][ac]),
                       &A[(size_t)am1 * K + k0 + BK + ac], az1);
            cp_async16((uint32_t)__cvta_generic_to_shared(&Bs[nb][br0][bc]),
                       &B[(size_t)(k0 + BK + br0) * N + bn + bc], 16);
            cp_async16((uint32_t)__cvta_generic_to_shared(&Bs[nb][br1][bc]),
                       &B[(size_t)(k0 + BK + br1) * N + bn + bc], 16);
            asm volatile("cp.async.commit_group;\n");
        }

#pragma unroll
        for (int ks = 0; ks < BK; ks += 8) {
            uint32_t ahi[2][4], alo[2][4], bhi[4][2], blo[4][2];
#pragma unroll
            for (int mt = 0; mt < 2; mt++) {
                int r0 = wm * 32 + mt * 16 + gid;
                tf32_split(As[buf][r0    ][ks + tig    ], ahi[mt][0], alo[mt][0]);
                tf32_split(As[buf][r0 + 8][ks + tig    ], ahi[mt][1], alo[mt][1]);
                tf32_split(As[buf][r0    ][ks + tig + 4], ahi[mt][2], alo[mt][2]);
                tf32_split(As[buf][r0 + 8][ks + tig + 4], ahi[mt][3], alo[mt][3]);
            }
#pragma unroll
            for (int nt = 0; nt < 4; nt++) {
                int n = wn * 32 + nt * 8 + gid;
                tf32_split(Bs[buf][ks + tig    ][n], bhi[nt][0], blo[nt][0]);
                tf32_split(Bs[buf][ks + tig + 4][n], bhi[nt][1], blo[nt][1]);
            }
#pragma unroll
            for (int mt = 0; mt < 2; mt++)
#pragma unroll
                for (int nt = 0; nt < 4; nt++) {
                    mma_tf32(acc[mt][nt], ahi[mt], bhi[nt]);
                    mma_tf32(acc[mt][nt], ahi[mt], blo[nt]);
                    mma_tf32(acc[mt][nt], alo[mt], bhi[nt]);
                }
        }

        if (more) {
            asm volatile("cp.async.wait_group 0;\n");
            __syncthreads();
            buf ^= 1;
        }
    }

    // epilogue: rowscale by dinv
#pragma unroll
    for (int mt = 0; mt < 2; mt++) {
        int r0 = bm + wm * 32 + mt * 16 + gid;
        int r1 = r0 + 8;
        float rs0 = (r0 < M) ? g_dinv[r0] : 0.f;
        float rs1 = (r1 < M) ? g_dinv[r1] : 0.f;
#pragma unroll
        for (int nt = 0; nt < 4; nt++) {
            int c = bn + wn * 32 + nt * 8 + tig * 2;
            if (r0 < M) {
                float2 v0 = make_float2(acc[mt][nt][0] * rs0, acc[mt][nt][1] * rs0);
                *reinterpret_cast<float2*>(&U[(size_t)r0 * N + c]) = v0;
            }
            if (r1 < M) {
                float2 v1 = make_float2(acc[mt][nt][2] * rs1, acc[mt][nt][3] * rs1);
                *reinterpret_cast<float2*>(&U[(size_t)r1 * N + c]) = v1;
            }
        }
    }
}

// ---------------- CSR gather conv: h[m] = relu(dinv[m]*(u[m]+Σu[s]) + b) ---
__global__ __launch_bounds__(64)
void gather_relu_kernel(const float* __restrict__ bias, float* __restrict__ out) {
    int m = blockIdx.x;
    int f4 = threadIdx.x;                  // 0..63
    const float4* U4 = reinterpret_cast<const float4*>(g_u);
    int beg = g_off[m];
    int cnt = g_hist[m];
    float4 acc = U4[(size_t)m * 64 + f4];  // self loop
    int e = 0;
    for (; e + 4 <= cnt; e += 4) {
        int s0 = g_csr[beg + e + 0], s1 = g_csr[beg + e + 1];
        int s2 = g_csr[beg + e + 2], s3 = g_csr[beg + e + 3];
        float4 v0 = U4[(size_t)s0 * 64 + f4];
        float4 v1 = U4[(size_t)s1 * 64 + f4];
        float4 v2 = U4[(size_t)s2 * 64 + f4];
        float4 v3 = U4[(size_t)s3 * 64 + f4];
        acc.x += (v0.x + v1.x) + (v2.x + v3.x);
        acc.y += (v0.y + v1.y) + (v2.y + v3.y);
        acc.z += (v0.z + v1.z) + (v2.z + v3.z);
        acc.w += (v0.w + v1.w) + (v2.w + v3.w);
    }
    for (; e < cnt; e++) {
        int s = g_csr[beg + e];
        float4 v = U4[(size_t)s * 64 + f4];
        acc.x += v.x; acc.y += v.y; acc.z += v.z; acc.w += v.w;
    }
    float di = g_dinv[m];
    float4 bb = reinterpret_cast<const float4*>(bias)[f4];
    float4 h;
    h.x = fmaxf(di * acc.x + bb.x, 0.f);
    h.y = fmaxf(di * acc.y + bb.y, 0.f);
    h.z = fmaxf(di * acc.z + bb.z, 0.f);
    h.w = fmaxf(di * acc.w + bb.w, 0.f);
    reinterpret_cast<float4*>(out)[(size_t)m * 64 + f4] = h;
}

// conv2 gather fused with mean-pool accumulation (h never materialized)
__global__ __launch_bounds__(64)
void gather_pool_kernel(const float* __restrict__ bias, const int* __restrict__ batch) {
    int m = blockIdx.x;
    int f4 = threadIdx.x;
    const float4* U4 = reinterpret_cast<const float4*>(g_u);
    int beg = g_off[m];
    int cnt = g_hist[m];
    float4 acc = U4[(size_t)m * 64 + f4];
    int e = 0;
    for (; e + 4 <= cnt; e += 4) {
        int s0 = g_csr[beg + e + 0], s1 = g_csr[beg + e + 1];
        int s2 = g_csr[beg + e + 2], s3 = g_csr[beg + e + 3];
        float4 v0 = U4[(size_t)s0 * 64 + f4];
        float4 v1 = U4[(size_t)s1 * 64 + f4];
        float4 v2 = U4[(size_t)s2 * 64 + f4];
        float4 v3 = U4[(size_t)s3 * 64 + f4];
        acc.x += (v0.x + v1.x) + (v2.x + v3.x);
        acc.y += (v0.y + v1.y) + (v2.y + v3.y);
        acc.z += (v0.z + v1.z) + (v2.z + v3.z);
        acc.w += (v0.w + v1.w) + (v2.w + v3.w);
    }
    for (; e < cnt; e++) {
        int s = g_csr[beg + e];
        float4 v = U4[(size_t)s * 64 + f4];
        acc.x += v.x; acc.y += v.y; acc.z += v.z; acc.w += v.w;
    }
    float di = g_dinv[m];
    float4 bb = reinterpret_cast<const float4*>(bias)[f4];
    float hx = fmaxf(di * acc.x + bb.x, 0.f);
    float hy = fmaxf(di * acc.y + bb.y, 0.f);
    float hz = fmaxf(di * acc.z + bb.z, 0.f);
    float hw = fmaxf(di * acc.w + bb.w, 0.f);
    int b = batch[m];
    float* sbase = &g_sums[(size_t)b * H_DIM + f4 * 4];
    atomicAdd(sbase + 0, hx);
    atomicAdd(sbase + 1, hy);
    atomicAdd(sbase + 2, hz);
    atomicAdd(sbase + 3, hw);
    if (f4 == 0) atomicAdd(&g_cnt[b], 1.0f);
}

__global__ void pool_div_kernel() {
    int g = blockIdx.x;
    int f = threadIdx.x;
    g_hg[g * H_DIM + f] = g_sums[g * H_DIM + f] / fmaxf(g_cnt[g], 1.0f);
}

// ---------------- mu / logvar / z ----------------
__global__ void muz_kernel(const float* __restrict__ Wmu, const float* __restrict__ bmu,
                           const float* __restrict__ Wlv, const float* __restrict__ blv,
                           const float* __restrict__ eps,
                           float* __restrict__ out_mu, float* __restrict__ out_lv) {
    int g = blockIdx.x;
    int l = threadIdx.x;            // 64
    __shared__ float sh[H_DIM];
    for (int k = l; k < H_DIM; k += L_DIM) sh[k] = g_hg[g * H_DIM + k];
    __syncthreads();
    float mu = bmu[l], lv = blv[l];
    for (int k = 0; k < H_DIM; k++) {
        float h = sh[k];
        mu += h * Wmu[k * L_DIM + l];
        lv += h * Wlv[k * L_DIM + l];
    }
    out_mu[g * L_DIM + l] = mu;
    out_lv[g * L_DIM + l] = lv;
    g_z[g * L_DIM + l] = mu + eps[g * L_DIM + l] * expf(0.5f * lv);
}

// ---------------- decoder dense+relu ----------------
__global__ void dense_relu_kernel(const float* __restrict__ X,
                                  const float* __restrict__ W,
                                  const float* __restrict__ b,
                                  float* __restrict__ Y, int K) {
    int g = blockIdx.x;
    int n = threadIdx.x;            // 256
    __shared__ float sx[H_DIM];
    if (n < K) sx[n] = X[g * K + n];
    __syncthreads();
    float acc = b[n];
    for (int k = 0; k < K; k++) acc += sx[k] * W[k * H_DIM + n];
    Y[g * H_DIM + n] = fmaxf(acc, 0.f);
}

// ---------------- adjacency decode ----------------
__global__ void pairmap_kernel() {
    int i = blockIdx.x;             // 0..99
    int j = threadIdx.x;            // 0..127
    if (j > i && j < MAXN) {
        int p = i * 99 - (i * (i - 1)) / 2 + (j - i - 1);
        g_pi[p] = i;
        g_pj[p] = j;
    }
}

__global__ void diag_kernel(float* __restrict__ adj) {
    int g = blockIdx.x;
    int i = threadIdx.x;
    if (i < MAXN)
        adj[(size_t)g * MAXN * MAXN + i * MAXN + i] = 0.f;
}

#define GCH 8
__global__ __launch_bounds__(128)
void adj_kernel(const float* __restrict__ D3, const float* __restrict__ db3,
                float* __restrict__ adj) {
    int p  = blockIdx.x * 128 + threadIdx.x;
    int g0 = blockIdx.y * GCH;
    __shared__ float sd2[GCH][H_DIM];
    for (int idx = threadIdx.x; idx < GCH * H_DIM; idx += 128)
        sd2[idx >> 8][idx & 255] = g_d2[(size_t)(g0 + (idx >> 8)) * H_DIM + (idx & 255)];
    __syncthreads();
    if (p >= NPAIR) return;
    int i = g_pi[p], j = g_pj[p];
    float bb = db3[p];
    float acc[GCH];
#pragma unroll
    for (int gg = 0; gg < GCH; gg++) acc[gg] = bb;
    for (int k = 0; k < H_DIM; k++) {
        float w = D3[(size_t)k * NPAIR + p];
#pragma unroll
        for (int gg = 0; gg < GCH; gg++) acc[gg] += sd2[gg][k] * w;
    }
#pragma unroll
    for (int gg = 0; gg < GCH; gg++) {
        float prob = 1.0f / (1.0f + expf(-acc[gg]));
        size_t base = (size_t)(g0 + gg) * (MAXN * MAXN);
        adj[base + i * MAXN + j] = prob;
        adj[base + j * MAXN + i] = prob;
    }
}

// ---------------- launch ----------------
extern "C" void kernel_launch(void* const* d_in, const int* in_sizes, int n_in,
                              void* d_out, int out_size) {
    const float* x    = (const float*)d_in[0];
    const int*   ei   = (const int*)  d_in[1];
    const int*   batch= (const int*)  d_in[2];
    const float* eps  = (const float*)d_in[3];
    const float* W1   = (const float*)d_in[4];
    const float* b1   = (const float*)d_in[5];
    const float* W2   = (const float*)d_in[6];
    const float* b2   = (const float*)d_in[7];
    const float* Wmu  = (const float*)d_in[8];
    const float* bmu  = (const float*)d_in[9];
    const float* Wlv  = (const float*)d_in[10];
    const float* blv  = (const float*)d_in[11];
    const float* D1   = (const float*)d_in[12];
    const float* db1  = (const float*)d_in[13];
    const float* D2   = (const float*)d_in[14];
    const float* db2  = (const float*)d_in[15];
    const float* D3   = (const float*)d_in[16];
    const float* db3  = (const float*)d_in[17];

    const int* src = ei;
    const int* dst = ei + N_EDGES;

    float* out      = (float*)d_out;
    float* out_adj  = out;                                        // 200*100*100
    float* out_mu   = out + (size_t)N_GRAPHS * MAXN * MAXN;       // 200*64
    float* out_lv   = out_mu + (size_t)N_GRAPHS * L_DIM;          // 200*64

    float *p_u, *p_h, *p_z, *p_d1, *p_d2;
    cudaGetSymbolAddress((void**)&p_u,  g_u);
    cudaGetSymbolAddress((void**)&p_h,  g_h);
    cudaGetSymbolAddress((void**)&p_z,  g_z);
    cudaGetSymbolAddress((void**)&p_d1, g_d1);
    cudaGetSymbolAddress((void**)&p_d2, g_d2);

    // Lazy-created side stream + events (first call is the uncaptured
    // correctness run; capture reuses them — no creation under capture).
    static cudaStream_t s_side = nullptr;
    static cudaEvent_t  ev_fork = nullptr, ev_join = nullptr;
    if (s_side == nullptr) {
        cudaStreamCreateWithFlags(&s_side, cudaStreamNonBlocking);
        cudaEventCreateWithFlags(&ev_fork, cudaEventDisableTiming);
        cudaEventCreateWithFlags(&ev_join, cudaEventDisableTiming);
    }

    // CSR prefix (dinv needed by gemm1 epilogue) on main stream
    zero_kernel<<<(N_GRAPHS * H_DIM + 255) / 256, 256>>>();
    hist_kernel<<<(N_EDGES + 255) / 256, 256>>>(dst);
    scan_kernel<<<1, SCAN_T>>>();

    // fork: fill + pairmap + diag run concurrently with gemm1
    cudaEventRecord(ev_fork, 0);
    cudaStreamWaitEvent(s_side, ev_fork, 0);
    fill_kernel<<<(N_EDGES + 255) / 256, 256, 0, s_side>>>(src, dst);
    pairmap_kernel<<<MAXN, 128, 0, s_side>>>();
    diag_kernel<<<N_GRAPHS, 128, 0, s_side>>>(out_adj);
    cudaEventRecord(ev_join, s_side);

    dim3 ggrid(H_DIM / BN, (N_NODES + BM - 1) / BM);

    // conv1 gemm (needs only dinv) overlaps the side stream
    gemm_tf32_rowscale_kernel<<<ggrid, 128>>>(x, W1, p_u, N_NODES, IN_DIM, H_DIM);

    // join: gather needs the CSR fill
    cudaStreamWaitEvent(0, ev_join, 0);
    gather_relu_kernel<<<N_NODES, 64>>>(b1, p_h);

    // conv2: gemm -> gather fused with mean-pool accumulation
    gemm_tf32_rowscale_kernel<<<ggrid, 128>>>(p_h, W2, p_u, N_NODES, H_DIM, H_DIM);
    gather_pool_kernel<<<N_NODES, 64>>>(b2, batch);
    pool_div_kernel<<<N_GRAPHS, H_DIM>>>();

    // VAE head
    muz_kernel<<<N_GRAPHS, L_DIM>>>(Wmu, bmu, Wlv, blv, eps, out_mu, out_lv);

    // decoder MLP
    dense_relu_kernel<<<N_GRAPHS, H_DIM>>>(p_z,  D1, db1, p_d1, L_DIM);
    dense_relu_kernel<<<N_GRAPHS, H_DIM>>>(p_d1, D2, db2, p_d2, H_DIM);

    // adjacency
    adj_kernel<<<dim3((NPAIR + 127) / 128, N_GRAPHS / GCH), 128>>>(D3, db3, out_adj);
}

// round 17
// speedup vs baseline: 1.1898x; 1.0613x over previous
#include <cuda_runtime.h>
#include <cuda_fp16.h>
#include <cstdint>
#include <cmath>

// ---------------- problem constants ----------------
#define N_NODES   20000
#define N_EDGES   320000
#define N_GRAPHS  200
#define MAXN      100
#define NPAIR     4950          // 100*99/2
#define IN_DIM    128
#define H_DIM     256
#define L_DIM     64

// ---------------- scratch (device globals; no allocation allowed) ----------
__device__ __align__(128) int    g_hist[N_NODES];            // in-degree
__device__ __align__(128) int    g_off [N_NODES];            // CSR exclusive offsets
__device__ __align__(128) int    g_cur [N_NODES];            // fill cursors
__device__ __align__(128) int    g_csr [N_EDGES];            // src ids grouped by dst
__device__ __align__(128) float  g_dinv[N_NODES];            // rsqrt(deg+1)
__device__ __align__(128) __half g_u   [N_NODES * H_DIM];    // (A@B)*dinv[row], fp16
__device__ __align__(128) float  g_h   [N_NODES * H_DIM];    // conv1 output
__device__ __align__(128) float  g_sums[N_GRAPHS * H_DIM];
__device__ __align__(128) float  g_cnt [N_GRAPHS];
__device__ __align__(128) float  g_hg  [N_GRAPHS * H_DIM];
__device__ __align__(128) float  g_z   [N_GRAPHS * L_DIM];
__device__ __align__(128) float  g_d1  [N_GRAPHS * H_DIM];
__device__ __align__(128) float  g_d2  [N_GRAPHS * H_DIM];
__device__ __align__(128) int    g_pi  [NPAIR];
__device__ __align__(128) int    g_pj  [NPAIR];

// ---------------- zero scratch ----------------
__global__ void zero_kernel() {
    int i = blockIdx.x * blockDim.x + threadIdx.x;
    if (i < N_NODES) { g_hist[i] = 0; g_cur[i] = 0; }
    if (i < N_GRAPHS * H_DIM) g_sums[i] = 0.f;
    if (i < N_GRAPHS) g_cnt[i] = 0.f;
}

// ---------------- CSR build ----------------
__global__ void hist_kernel(const int* __restrict__ dst) {
    int e = blockIdx.x * blockDim.x + threadIdx.x;
    if (e < N_EDGES) atomicAdd(&g_hist[dst[e]], 1);
}

#define SCAN_T 1024
#define SCAN_CH 20   // 1024*20 >= 20000
__global__ __launch_bounds__(SCAN_T)
void scan_kernel() {
    __shared__ int sp[SCAN_T];
    int t = threadIdx.x;
    int start = t * SCAN_CH;
    int s = 0;
#pragma unroll
    for (int c = 0; c < SCAN_CH; c++) {
        int i = start + c;
        if (i < N_NODES) s += g_hist[i];
    }
    sp[t] = s;
    __syncthreads();
    for (int off = 1; off < SCAN_T; off <<= 1) {
        int v = (t >= off) ? sp[t - off] : 0;
        __syncthreads();
        sp[t] += v;
        __syncthreads();
    }
    int base = sp[t] - s;
#pragma unroll
    for (int c = 0; c < SCAN_CH; c++) {
        int i = start + c;
        if (i < N_NODES) { g_off[i] = base; base += g_hist[i]; }
    }
    for (int i = t; i < N_NODES; i += SCAN_T)
        g_dinv[i] = rsqrtf((float)g_hist[i] + 1.0f);
}

__global__ void fill_kernel(const int* __restrict__ src, const int* __restrict__ dst) {
    int e = blockIdx.x * blockDim.x + threadIdx.x;
    if (e >= N_EDGES) return;
    int d = dst[e];
    int pos = atomicAdd(&g_cur[d], 1);
    g_csr[g_off[d] + pos] = src[e];
}

// ---------------- tf32 MMA GEMM: U(fp16) = (A@B) * dinv[row] --------------
// 3-term split: D += Ahi*Bhi + Ahi*Blo + Alo*Bhi.
// cp.async double-buffered smem pipeline.
#define BM 64
#define BN 64
#define BK 16
#define AP 20   // As pitch
#define BP 72   // Bs pitch

__device__ __forceinline__ uint32_t f2tf32(float x) {
    uint32_t r;
    asm("cvt.rna.tf32.f32 %0, %1;" : "=r"(r) : "f"(x));
    return r;
}
__device__ __forceinline__ void tf32_split(float x, uint32_t& hi, uint32_t& lo) {
    hi = f2tf32(x);
    float hf = __uint_as_float(hi);
    lo = f2tf32(x - hf);
}
__device__ __forceinline__ void mma_tf32(float* c, const uint32_t* a, const uint32_t* b) {
    asm volatile(
        "mma.sync.aligned.m16n8k8.row.col.f32.tf32.tf32.f32 "
        "{%0,%1,%2,%3},{%4,%5,%6,%7},{%8,%9},{%0,%1,%2,%3};"
        : "+f"(c[0]), "+f"(c[1]), "+f"(c[2]), "+f"(c[3])
        : "r"(a[0]), "r"(a[1]), "r"(a[2]), "r"(a[3]), "r"(b[0]), "r"(b[1]));
}
__device__ __forceinline__ void cp_async16(uint32_t saddr, const void* g, int src_sz) {
    asm volatile("cp.async.ca.shared.global [%0], [%1], 16, %2;\n"
                 :: "r"(saddr), "l"(g), "r"(src_sz));
}

__global__ __launch_bounds__(128)
void gemm_tf32_rowscale_kernel(const float* __restrict__ A,
                               const float* __restrict__ B,
                               __half* __restrict__ U,
                               int M, int K, int N) {
    __shared__ float As[2][BM][AP];
    __shared__ float Bs[2][BK][BP];
    const int bm   = blockIdx.y * BM;
    const int bn   = blockIdx.x * BN;
    const int tid  = threadIdx.x;
    const int wid  = tid >> 5;
    const int lane = tid & 31;
    const int wm   = wid >> 1;        // 0..1
    const int wn   = wid & 1;         // 0..1
    const int gid  = lane >> 2;       // 0..7
    const int tig  = lane & 3;        // 0..3

    const int ar0 = tid >> 2,         ac = (tid & 3) * 4;
    const int ar1 = (tid + 128) >> 2;
    const int br0 = tid >> 4,         bc = (tid & 15) * 4;
    const int br1 = (tid + 128) >> 4;
    const int am0 = (bm + ar0 < M) ? (bm + ar0) : (M - 1);
    const int am1 = (bm + ar1 < M) ? (bm + ar1) : (M - 1);
    const int az0 = (bm + ar0 < M) ? 16 : 0;
    const int az1 = (bm + ar1 < M) ? 16 : 0;

    float acc[2][4][4];
#pragma unroll
    for (int mt = 0; mt < 2; mt++)
#pragma unroll
        for (int nt = 0; nt < 4; nt++)
#pragma unroll
            for (int i = 0; i < 4; i++) acc[mt][nt][i] = 0.f;

    // issue tile 0
    {
        cp_async16((uint32_t)__cvta_generic_to_shared(&As[0][ar0][ac]),
                   &A[(size_t)am0 * K + ac], az0);
        cp_async16((uint32_t)__cvta_generic_to_shared(&As[0][ar1][ac]),
                   &A[(size_t)am1 * K + ac], az1);
        cp_async16((uint32_t)__cvta_generic_to_shared(&Bs[0][br0][bc]),
                   &B[(size_t)br0 * N + bn + bc], 16);
        cp_async16((uint32_t)__cvta_generic_to_shared(&Bs[0][br1][bc]),
                   &B[(size_t)br1 * N + bn + bc], 16);
        asm volatile("cp.async.commit_group;\n");
    }
    asm volatile("cp.async.wait_group 0;\n");
    __syncthreads();

    int buf = 0;
    for (int k0 = 0; k0 < K; k0 += BK) {
        const bool more = (k0 + BK < K);
        if (more) {
            int nb = buf ^ 1;
            cp_async16((uint32_t)__cvta_generic_to_shared(&As[nb][ar0][ac]),
                       &A[(size_t)am0 * K + k0 + BK + ac], az0);
            cp_async16((uint32_t)__cvta_generic_to_shared(&As[nb][ar1][ac]),
                       &A[(size_t)am1 * K + k0 + BK + ac], az1);
            cp_async16((uint32_t)__cvta_generic_to_shared(&Bs[nb][br0][bc]),
                       &B[(size_t)(k0 + BK + br0) * N + bn + bc], 16);
            cp_async16((uint32_t)__cvta_generic_to_shared(&Bs[nb][br1][bc]),
                       &B[(size_t)(k0 + BK + br1) * N + bn + bc], 16);
            asm volatile("cp.async.commit_group;\n");
        }

#pragma unroll
        for (int ks = 0; ks < BK; ks += 8) {
            uint32_t ahi[2][4], alo[2][4], bhi[4][2], blo[4][2];
#pragma unroll
            for (int mt = 0; mt < 2; mt++) {
                int r0 = wm * 32 + mt * 16 + gid;
                tf32_split(As[buf][r0    ][ks + tig    ], ahi[mt][0], alo[mt][0]);
                tf32_split(As[buf][r0 + 8][ks + tig    ], ahi[mt][1], alo[mt][1]);
                tf32_split(As[buf][r0    ][ks + tig + 4], ahi[mt][2], alo[mt][2]);
                tf32_split(As[buf][r0 + 8][ks + tig + 4], ahi[mt][3], alo[mt][3]);
            }
#pragma unroll
            for (int nt = 0; nt < 4; nt++) {
                int n = wn * 32 + nt * 8 + gid;
                tf32_split(Bs[buf][ks + tig    ][n], bhi[nt][0], blo[nt][0]);
                tf32_split(Bs[buf][ks + tig + 4][n], bhi[nt][1], blo[nt][1]);
            }
#pragma unroll
            for (int mt = 0; mt < 2; mt++)
#pragma unroll
                for (int nt = 0; nt < 4; nt++) {
                    mma_tf32(acc[mt][nt], ahi[mt], bhi[nt]);
                    mma_tf32(acc[mt][nt], ahi[mt], blo[nt]);
                    mma_tf32(acc[mt][nt], alo[mt], bhi[nt]);
                }
        }

        if (more) {
            asm volatile("cp.async.wait_group 0;\n");
            __syncthreads();
            buf ^= 1;
        }
    }

    // epilogue: rowscale by dinv, emit fp16 (half2 per column pair)
#pragma unroll
    for (int mt = 0; mt < 2; mt++) {
        int r0 = bm + wm * 32 + mt * 16 + gid;
        int r1 = r0 + 8;
        float rs0 = (r0 < M) ? g_dinv[r0] : 0.f;
        float rs1 = (r1 < M) ? g_dinv[r1] : 0.f;
#pragma unroll
        for (int nt = 0; nt < 4; nt++) {
            int c = bn + wn * 32 + nt * 8 + tig * 2;
            if (r0 < M) {
                __half2 v0 = __float22half2_rn(
                    make_float2(acc[mt][nt][0] * rs0, acc[mt][nt][1] * rs0));
                *reinterpret_cast<__half2*>(&U[(size_t)r0 * N + c]) = v0;
            }
            if (r1 < M) {
                __half2 v1 = __float22half2_rn(
                    make_float2(acc[mt][nt][2] * rs1, acc[mt][nt][3] * rs1));
                *reinterpret_cast<__half2*>(&U[(size_t)r1 * N + c]) = v1;
            }
        }
    }
}

// ---------------- CSR gather conv: h[m] = relu(dinv[m]*(u[m]+Σu[s]) + b) ---
// u rows are fp16 (512B/row); 64 threads/node, 4 halves (8B) per thread.
__device__ __forceinline__ void acc_half4(float4& a, uint2 raw) {
    float2 p0 = __half22float2(*reinterpret_cast<__half2*>(&raw.x));
    float2 p1 = __half22float2(*reinterpret_cast<__half2*>(&raw.y));
    a.x += p0.x; a.y += p0.y; a.z += p1.x; a.w += p1.y;
}

__global__ __launch_bounds__(64)
void gather_relu_kernel(const float* __restrict__ bias, float* __restrict__ out) {
    int m = blockIdx.x;
    int t = threadIdx.x;                   // 0..63, 4 features each
    const uint2* U4 = reinterpret_cast<const uint2*>(g_u);   // 8B = 4 halves
    int beg = g_off[m];
    int cnt = g_hist[m];
    float4 acc = make_float4(0.f, 0.f, 0.f, 0.f);
    acc_half4(acc, U4[(size_t)m * 64 + t]);   // self loop
    int e = 0;
    for (; e + 4 <= cnt; e += 4) {
        int s0 = g_csr[beg + e + 0], s1 = g_csr[beg + e + 1];
        int s2 = g_csr[beg + e + 2], s3 = g_csr[beg + e + 3];
        uint2 r0 = U4[(size_t)s0 * 64 + t];
        uint2 r1 = U4[(size_t)s1 * 64 + t];
        uint2 r2 = U4[(size_t)s2 * 64 + t];
        uint2 r3 = U4[(size_t)s3 * 64 + t];
        acc_half4(acc, r0); acc_half4(acc, r1);
        acc_half4(acc, r2); acc_half4(acc, r3);
    }
    for (; e < cnt; e++) {
        int s = g_csr[beg + e];
        acc_half4(acc, U4[(size_t)s * 64 + t]);
    }
    float di = g_dinv[m];
    float4 bb = reinterpret_cast<const float4*>(bias)[t];
    float4 h;
    h.x = fmaxf(di * acc.x + bb.x, 0.f);
    h.y = fmaxf(di * acc.y + bb.y, 0.f);
    h.z = fmaxf(di * acc.z + bb.z, 0.f);
    h.w = fmaxf(di * acc.w + bb.w, 0.f);
    reinterpret_cast<float4*>(out)[(size_t)m * 64 + t] = h;
}

// conv2 gather fused with mean-pool accumulation (h never materialized)
__global__ __launch_bounds__(64)
void gather_pool_kernel(const float* __restrict__ bias, const int* __restrict__ batch) {
    int m = blockIdx.x;
    int t = threadIdx.x;
    const uint2* U4 = reinterpret_cast<const uint2*>(g_u);
    int beg = g_off[m];
    int cnt = g_hist[m];
    float4 acc = make_float4(0.f, 0.f, 0.f, 0.f);
    acc_half4(acc, U4[(size_t)m * 64 + t]);
    int e = 0;
    for (; e + 4 <= cnt; e += 4) {
        int s0 = g_csr[beg + e + 0], s1 = g_csr[beg + e + 1];
        int s2 = g_csr[beg + e + 2], s3 = g_csr[beg + e + 3];
        uint2 r0 = U4[(size_t)s0 * 64 + t];
        uint2 r1 = U4[(size_t)s1 * 64 + t];
        uint2 r2 = U4[(size_t)s2 * 64 + t];
        uint2 r3 = U4[(size_t)s3 * 64 + t];
        acc_half4(acc, r0); acc_half4(acc, r1);
        acc_half4(acc, r2); acc_half4(acc, r3);
    }
    for (; e < cnt; e++) {
        int s = g_csr[beg + e];
        acc_half4(acc, U4[(size_t)s * 64 + t]);
    }
    float di = g_dinv[m];
    float4 bb = reinterpret_cast<const float4*>(bias)[t];
    float hx = fmaxf(di * acc.x + bb.x, 0.f);
    float hy = fmaxf(di * acc.y + bb.y, 0.f);
    float hz = fmaxf(di * acc.z + bb.z, 0.f);
    float hw = fmaxf(di * acc.w + bb.w, 0.f);
    int b = batch[m];
    float* sbase = &g_sums[(size_t)b * H_DIM + t * 4];
    atomicAdd(sbase + 0, hx);
    atomicAdd(sbase + 1, hy);
    atomicAdd(sbase + 2, hz);
    atomicAdd(sbase + 3, hw);
    if (t == 0) atomicAdd(&g_cnt[b], 1.0f);
}

__global__ void pool_div_kernel() {
    int g = blockIdx.x;
    int f = threadIdx.x;
    g_hg[g * H_DIM + f] = g_sums[g * H_DIM + f] / fmaxf(g_cnt[g], 1.0f);
}

// ---------------- mu / logvar / z ----------------
__global__ void muz_kernel(const float* __restrict__ Wmu, const float* __restrict__ bmu,
                           const float* __restrict__ Wlv, const float* __restrict__ blv,
                           const float* __restrict__ eps,
                           float* __restrict__ out_mu, float* __restrict__ out_lv) {
    int g = blockIdx.x;
    int l = threadIdx.x;            // 64
    __shared__ float sh[H_DIM];
    for (int k = l; k < H_DIM; k += L_DIM) sh[k] = g_hg[g * H_DIM + k];
    __syncthreads();
    float mu = bmu[l], lv = blv[l];
    for (int k = 0; k < H_DIM; k++) {
        float h = sh[k];
        mu += h * Wmu[k * L_DIM + l];
        lv += h * Wlv[k * L_DIM + l];
    }
    out_mu[g * L_DIM + l] = mu;
    out_lv[g * L_DIM + l] = lv;
    g_z[g * L_DIM + l] = mu + eps[g * L_DIM + l] * expf(0.5f * lv);
}

// ---------------- decoder dense+relu ----------------
__global__ void dense_relu_kernel(const float* __restrict__ X,
                                  const float* __restrict__ W,
                                  const float* __restrict__ b,
                                  float* __restrict__ Y, int K) {
    int g = blockIdx.x;
    int n = threadIdx.x;            // 256
    __shared__ float sx[H_DIM];
    if (n < K) sx[n] = X[g * K + n];
    __syncthreads();
    float acc = b[n];
    for (int k = 0; k < K; k++) acc += sx[k] * W[k * H_DIM + n];
    Y[g * H_DIM + n] = fmaxf(acc, 0.f);
}

// ---------------- adjacency decode ----------------
__global__ void pairmap_kernel() {
    int i = blockIdx.x;             // 0..99
    int j = threadIdx.x;            // 0..127
    if (j > i && j < MAXN) {
        int p = i * 99 - (i * (i - 1)) / 2 + (j - i - 1);
        g_pi[p] = i;
        g_pj[p] = j;
    }
}

__global__ void diag_kernel(float* __restrict__ adj) {
    int g = blockIdx.x;
    int i = threadIdx.x;
    if (i < MAXN)
        adj[(size_t)g * MAXN * MAXN + i * MAXN + i] = 0.f;
}

#define GCH 8
__global__ __launch_bounds__(128)
void adj_kernel(const float* __restrict__ D3, const float* __restrict__ db3,
                float* __restrict__ adj) {
    int p  = blockIdx.x * 128 + threadIdx.x;
    int g0 = blockIdx.y * GCH;
    __shared__ float sd2[GCH][H_DIM];
    for (int idx = threadIdx.x; idx < GCH * H_DIM; idx += 128)
        sd2[idx >> 8][idx & 255] = g_d2[(size_t)(g0 + (idx >> 8)) * H_DIM + (idx & 255)];
    __syncthreads();
    if (p >= NPAIR) return;
    int i = g_pi[p], j = g_pj[p];
    float bb = db3[p];
    float acc[GCH];
#pragma unroll
    for (int gg = 0; gg < GCH; gg++) acc[gg] = bb;
    for (int k = 0; k < H_DIM; k++) {
        float w = D3[(size_t)k * NPAIR + p];
#pragma unroll
        for (int gg = 0; gg < GCH; gg++) acc[gg] += sd2[gg][k] * w;
    }
#pragma unroll
    for (int gg = 0; gg < GCH; gg++) {
        float prob = 1.0f / (1.0f + expf(-acc[gg]));
        size_t base = (size_t)(g0 + gg) * (MAXN * MAXN);
        adj[base + i * MAXN + j] = prob;
        adj[base + j * MAXN + i] = prob;
    }
}

// ---------------- launch ----------------
extern "C" void kernel_launch(void* const* d_in, const int* in_sizes, int n_in,
                              void* d_out, int out_size) {
    const float* x    = (const float*)d_in[0];
    const int*   ei   = (const int*)  d_in[1];
    const int*   batch= (const int*)  d_in[2];
    const float* eps  = (const float*)d_in[3];
    const float* W1   = (const float*)d_in[4];
    const float* b1   = (const float*)d_in[5];
    const float* W2   = (const float*)d_in[6];
    const float* b2   = (const float*)d_in[7];
    const float* Wmu  = (const float*)d_in[8];
    const float* bmu  = (const float*)d_in[9];
    const float* Wlv  = (const float*)d_in[10];
    const float* blv  = (const float*)d_in[11];
    const float* D1   = (const float*)d_in[12];
    const float* db1  = (const float*)d_in[13];
    const float* D2   = (const float*)d_in[14];
    const float* db2  = (const float*)d_in[15];
    const float* D3   = (const float*)d_in[16];
    const float* db3  = (const float*)d_in[17];

    const int* src = ei;
    const int* dst = ei + N_EDGES;

    float* out      = (float*)d_out;
    float* out_adj  = out;                                        // 200*100*100
    float* out_mu   = out + (size_t)N_GRAPHS * MAXN * MAXN;       // 200*64
    float* out_lv   = out_mu + (size_t)N_GRAPHS * L_DIM;          // 200*64

    __half* p_u;
    float *p_h, *p_z, *p_d1, *p_d2;
    cudaGetSymbolAddress((void**)&p_u,  g_u);
    cudaGetSymbolAddress((void**)&p_h,  g_h);
    cudaGetSymbolAddress((void**)&p_z,  g_z);
    cudaGetSymbolAddress((void**)&p_d1, g_d1);
    cudaGetSymbolAddress((void**)&p_d2, g_d2);

    // Lazy-created side stream + events (first call is the uncaptured
    // correctness run; capture reuses them — no creation under capture).
    static cudaStream_t s_side = nullptr;
    static cudaEvent_t  ev_fork = nullptr, ev_join = nullptr;
    if (s_side == nullptr) {
        cudaStreamCreateWithFlags(&s_side, cudaStreamNonBlocking);
        cudaEventCreateWithFlags(&ev_fork, cudaEventDisableTiming);
        cudaEventCreateWithFlags(&ev_join, cudaEventDisableTiming);
    }

    // CSR prefix (dinv needed by gemm1 epilogue) on main stream
    zero_kernel<<<(N_GRAPHS * H_DIM + 255) / 256, 256>>>();
    hist_kernel<<<(N_EDGES + 255) / 256, 256>>>(dst);
    scan_kernel<<<1, SCAN_T>>>();

    // fork: fill + pairmap + diag run concurrently with gemm1
    cudaEventRecord(ev_fork, 0);
    cudaStreamWaitEvent(s_side, ev_fork, 0);
    fill_kernel<<<(N_EDGES + 255) / 256, 256, 0, s_side>>>(src, dst);
    pairmap_kernel<<<MAXN, 128, 0, s_side>>>();
    diag_kernel<<<N_GRAPHS, 128, 0, s_side>>>(out_adj);
    cudaEventRecord(ev_join, s_side);

    dim3 ggrid(H_DIM / BN, (N_NODES + BM - 1) / BM);

    // conv1 gemm (needs only dinv) overlaps the side stream
    gemm_tf32_rowscale_kernel<<<ggrid, 128>>>(x, W1, p_u, N_NODES, IN_DIM, H_DIM);

    // join: gather needs the CSR fill
    cudaStreamWaitEvent(0, ev_join, 0);
    gather_relu_kernel<<<N_NODES, 64>>>(b1, p_h);

    // conv2: gemm -> gather fused with mean-pool accumulation
    gemm_tf32_rowscale_kernel<<<ggrid, 128>>>(p_h, W2, p_u, N_NODES, H_DIM, H_DIM);
    gather_pool_kernel<<<N_NODES, 64>>>(b2, batch);
    pool_div_kernel<<<N_GRAPHS, H_DIM>>>();

    // VAE head
    muz_kernel<<<N_GRAPHS, L_DIM>>>(Wmu, bmu, Wlv, blv, eps, out_mu, out_lv);

    // decoder MLP
    dense_relu_kernel<<<N_GRAPHS, H_DIM>>>(p_z,  D1, db1, p_d1, L_DIM);
    dense_relu_kernel<<<N_GRAPHS, H_DIM>>>(p_d1, D2, db2, p_d2, H_DIM);

    // adjacency
    adj_kernel<<<dim3((NPAIR + 127) / 128, N_GRAPHS / GCH), 128>>>(D3, db3, out_adj);
}